// round 2
// baseline (speedup 1.0000x reference)
#include <cuda_runtime.h>

#define HWD (96*96*96)        // 884736
#define NB  4
#define NVOX (NB*HWD)         // 3538944
#define Q4  (HWD/4)           // 221184 float4 groups per (b, channel)

__device__ double g_sum;
__device__ int    g_cnt;

__global__ void init_kernel() {
    g_sum = 0.0;
    g_cnt = 0;
}

__global__ void finalize_kernel(float* __restrict__ out) {
    double n = (double)g_cnt;
    if (n < 1.0) n = 1.0;
    out[0] = (float)(g_sum / n);
}

// Given the 6 unique entries of a symmetric 3x3 (already scaled+masked),
// return q (mean eigenvalue), p (spread), cp = cos(acos(r)/3).
__device__ __forceinline__ void eig_qpc(
    float a00, float a01, float a02, float a11, float a12, float a22,
    float& q, float& p, float& cp)
{
    q = (a00 + a11 + a22) * (1.0f / 3.0f);
    float c00 = a00 - q, c11 = a11 - q, c22 = a22 - q;
    float p2 = c00*c00 + c11*c11 + c22*c22
             + 2.0f * (a01*a01 + a02*a02 + a12*a12);
    p = sqrtf(p2 * (1.0f / 6.0f));
    float ps  = (p > 0.0f) ? p : 1.0f;
    float inv = 1.0f / ps;
    float b00 = c00*inv, b11 = c11*inv, b22 = c22*inv;
    float b01 = a01*inv, b02 = a02*inv, b12 = a12*inv;
    float det = b00*(b11*b22 - b12*b12)
              - b01*(b01*b22 - b12*b02)
              + b02*(b01*b12 - b11*b02);
    float r = 0.5f * det;
    r = fminf(fmaxf(r, -1.0f + 1e-7f), 1.0f - 1e-7f);
    float phi = acosf(r) * (1.0f / 3.0f);
    cp = __cosf(phi);   // phi in [0, pi/3]: fast-math cos is plenty accurate
}

__device__ __forceinline__ float f4_get(const float4& v, int lane) {
    switch (lane) {
        case 0: return v.x;
        case 1: return v.y;
        case 2: return v.z;
        default: return v.w;
    }
}

__global__ void __launch_bounds__(256)
ani_loss_kernel(const float*  __restrict__ input,
                const float*  __restrict__ target,
                const int*    __restrict__ mask,
                const float*  __restrict__ gt_mean,
                const float*  __restrict__ gt_std)
{
    int i = blockIdx.x * blockDim.x + threadIdx.x;   // one thread = 4 voxels

    float lsum = 0.0f;
    int   lcnt = 0;

    if (i < NVOX / 4) {
        int b = i / Q4;
        int s = i - b * Q4;

        const float4* in4 = (const float4*)input;
        const float4* tg4 = (const float4*)target;
        const int4*   mk4 = (const int4*)mask;

        int4 mi = mk4[b * Q4 + s];

        float4 xin[6], xtg[6];
        #pragma unroll
        for (int c = 0; c < 6; c++) {
            int off = (b * 6 + c) * Q4 + s;
            xin[c] = in4[off];
            xtg[c] = tg4[off];
        }

        float mean[6], stdv[6];
        #pragma unroll
        for (int c = 0; c < 6; c++) {
            mean[c] = __ldg(&gt_mean[c]);
            stdv[c] = __ldg(&gt_std[c]);
        }

        int mlane[4] = {mi.x, mi.y, mi.z, mi.w};

        #pragma unroll
        for (int lane = 0; lane < 4; lane++) {
            float mf = (float)mlane[lane];
            float ai[6], at[6];
            #pragma unroll
            for (int c = 0; c < 6; c++) {
                float vi = f4_get(xin[c], lane);
                float vt = f4_get(xtg[c], lane);
                ai[c] = fmaf(vi, stdv[c], mean[c]) * mf;
                at[c] = fmaf(vt, stdv[c], mean[c]) * mf;
            }
            float qi, pi, ci, qt, pt, ct;
            eig_qpc(ai[0], ai[1], ai[2], ai[3], ai[4], ai[5], qi, pi, ci);
            eig_qpc(at[0], at[1], at[2], at[3], at[4], at[5], qt, pt, ct);

            // input_ani = 3*p*cos(phi); target_ani = q - p*cos(phi)
            float d = fabsf(3.0f * pi * ci - (qt - pt * ct));
            lsum += d * mf;
            lcnt += mlane[lane];
        }
    }

    // warp reduce
    #pragma unroll
    for (int o = 16; o > 0; o >>= 1) {
        lsum += __shfl_down_sync(0xFFFFFFFFu, lsum, o);
        lcnt += __shfl_down_sync(0xFFFFFFFFu, lcnt, o);
    }

    __shared__ float ssum[8];
    __shared__ int   scnt[8];
    int wid = threadIdx.x >> 5;
    int lid = threadIdx.x & 31;
    if (lid == 0) { ssum[wid] = lsum; scnt[wid] = lcnt; }
    __syncthreads();

    if (wid == 0) {
        int nw = blockDim.x >> 5;
        float bs = (lid < nw) ? ssum[lid] : 0.0f;
        int   bc = (lid < nw) ? scnt[lid] : 0;
        #pragma unroll
        for (int o = 4; o > 0; o >>= 1) {
            bs += __shfl_down_sync(0xFFFFFFFFu, bs, o);
            bc += __shfl_down_sync(0xFFFFFFFFu, bc, o);
        }
        if (lid == 0) {
            atomicAdd(&g_sum, (double)bs);
            atomicAdd(&g_cnt, bc);
        }
    }
}

extern "C" void kernel_launch(void* const* d_in, const int* in_sizes, int n_in,
                              void* d_out, int out_size)
{
    const float* input   = (const float*)d_in[0];
    const float* target  = (const float*)d_in[1];
    const int*   mask    = (const int*)d_in[2];
    const float* gt_mean = (const float*)d_in[3];
    const float* gt_std  = (const float*)d_in[4];
    float* out = (float*)d_out;

    init_kernel<<<1, 1>>>();

    int nthreads = NVOX / 4;           // 884736
    int block = 256;
    int grid = (nthreads + block - 1) / block;   // 3456
    ani_loss_kernel<<<grid, block>>>(input, target, mask, gt_mean, gt_std);

    finalize_kernel<<<1, 1>>>(out);
}

// round 3
// speedup vs baseline: 1.2601x; 1.2601x over previous
#include <cuda_runtime.h>

#define HWD (96*96*96)        // 884736
#define NB  4
#define NVOX (NB*HWD)         // 3538944
#define Q4  (HWD/4)           // 221184 float4 groups per (b, channel)
#define BLOCK 256
#define GRID  (NVOX / 4 / BLOCK)   // 3456, exact

__device__ double       g_sum    = 0.0;
__device__ int          g_cnt    = 0;
__device__ unsigned int g_retire = 0u;

// Given the 6 unique entries of a symmetric 3x3, return q (mean eigenvalue),
// p (spread), cp = cos(acos(r)/3). Normalization folded into det via rs^3.
__device__ __forceinline__ void eig_qpc(
    float a00, float a01, float a02, float a11, float a12, float a22,
    float& q, float& p, float& cp)
{
    q = (a00 + a11 + a22) * (1.0f / 3.0f);
    float c00 = a00 - q, c11 = a11 - q, c22 = a22 - q;
    float p2 = c00*c00 + c11*c11 + c22*c22
             + 2.0f * (a01*a01 + a02*a02 + a12*a12);
    float p2s = p2 * (1.0f / 6.0f);
    float rs  = (p2s > 0.0f) ? rsqrtf(p2s) : 0.0f;   // MUFU.RSQ
    p = p2s * rs;                                     // = sqrt(p2/6)

    // det(C) where C = A - q*I  (off-diagonals unchanged)
    float detC = c00 * (c11*c22 - a12*a12)
               - a01 * (a01*c22 - a12*a02)
               + a02 * (a01*a12 - c11*a02);
    float rs3 = rs * rs * rs;
    float r = 0.5f * detC * rs3;                      // = 0.5*det(C/ps)
    r = fminf(fmaxf(r, -1.0f + 1e-7f), 1.0f - 1e-7f);
    float phi = acosf(r) * (1.0f / 3.0f);
    cp = __cosf(phi);   // phi in [0, pi/3]: fast cos is plenty accurate
}

__device__ __forceinline__ float f4_get(const float4& v, int lane) {
    switch (lane) {
        case 0: return v.x;
        case 1: return v.y;
        case 2: return v.z;
        default: return v.w;
    }
}

__global__ void __launch_bounds__(BLOCK)
ani_loss_kernel(const float*  __restrict__ input,
                const float*  __restrict__ target,
                const int*    __restrict__ mask,
                const float*  __restrict__ gt_mean,
                const float*  __restrict__ gt_std,
                float*        __restrict__ out)
{
    int i = blockIdx.x * blockDim.x + threadIdx.x;   // one thread = 4 voxels
    int b = i / Q4;
    int s = i - b * Q4;

    const float4* in4 = (const float4*)input;
    const float4* tg4 = (const float4*)target;
    const int4*   mk4 = (const int4*)mask;

    int4 mi = __ldcs(&mk4[b * Q4 + s]);

    float4 xin[6], xtg[6];
    #pragma unroll
    for (int c = 0; c < 6; c++) {
        int off = (b * 6 + c) * Q4 + s;
        xin[c] = __ldcs(&in4[off]);
        xtg[c] = __ldcs(&tg4[off]);
    }

    float mean[6], stdv[6];
    #pragma unroll
    for (int c = 0; c < 6; c++) {
        mean[c] = __ldg(&gt_mean[c]);
        stdv[c] = __ldg(&gt_std[c]);
    }

    int mlane[4] = {mi.x, mi.y, mi.z, mi.w};

    float lsum = 0.0f;
    int   lcnt = 0;

    #pragma unroll
    for (int lane = 0; lane < 4; lane++) {
        float ai[6], at[6];
        #pragma unroll
        for (int c = 0; c < 6; c++) {
            ai[c] = fmaf(f4_get(xin[c], lane), stdv[c], mean[c]);
            at[c] = fmaf(f4_get(xtg[c], lane), stdv[c], mean[c]);
        }
        float qi, pi, ci, qt, pt, ct;
        eig_qpc(ai[0], ai[1], ai[2], ai[3], ai[4], ai[5], qi, pi, ci);
        eig_qpc(at[0], at[1], at[2], at[3], at[4], at[5], qt, pt, ct);

        // input_ani = 3*p*cos(phi); target_ani = q - p*cos(phi)
        float mf = (float)mlane[lane];
        float d = fabsf(3.0f * pi * ci - (qt - pt * ct));
        lsum += d * mf;
        lcnt += mlane[lane];
    }

    // warp reduce
    #pragma unroll
    for (int o = 16; o > 0; o >>= 1) {
        lsum += __shfl_down_sync(0xFFFFFFFFu, lsum, o);
        lcnt += __shfl_down_sync(0xFFFFFFFFu, lcnt, o);
    }

    __shared__ float ssum[8];
    __shared__ int   scnt[8];
    __shared__ bool  isLast;
    int wid = threadIdx.x >> 5;
    int lid = threadIdx.x & 31;
    if (lid == 0) { ssum[wid] = lsum; scnt[wid] = lcnt; }
    __syncthreads();

    if (wid == 0) {
        float bs = (lid < (BLOCK >> 5)) ? ssum[lid] : 0.0f;
        int   bc = (lid < (BLOCK >> 5)) ? scnt[lid] : 0;
        #pragma unroll
        for (int o = 4; o > 0; o >>= 1) {
            bs += __shfl_down_sync(0xFFFFFFFFu, bs, o);
            bc += __shfl_down_sync(0xFFFFFFFFu, bc, o);
        }
        if (lid == 0) {
            atomicAdd(&g_sum, (double)bs);
            atomicAdd(&g_cnt, bc);
            __threadfence();
            unsigned t = atomicAdd(&g_retire, 1u);
            isLast = (t == (unsigned)(gridDim.x - 1));
        }
    }
    __syncthreads();

    // Last block finalizes and resets accumulators (graph-replay safe).
    if (isLast && threadIdx.x == 0) {
        double s_tot = atomicAdd(&g_sum, 0.0);
        int    c_tot = atomicAdd(&g_cnt, 0);
        double n = (c_tot < 1) ? 1.0 : (double)c_tot;
        out[0] = (float)(s_tot / n);
        atomicExch((unsigned long long*)&g_sum, 0ull);
        atomicExch(&g_cnt, 0);
        __threadfence();
        atomicExch(&g_retire, 0u);
    }
}

extern "C" void kernel_launch(void* const* d_in, const int* in_sizes, int n_in,
                              void* d_out, int out_size)
{
    const float* input   = (const float*)d_in[0];
    const float* target  = (const float*)d_in[1];
    const int*   mask    = (const int*)d_in[2];
    const float* gt_mean = (const float*)d_in[3];
    const float* gt_std  = (const float*)d_in[4];
    float* out = (float*)d_out;

    ani_loss_kernel<<<GRID, BLOCK>>>(input, target, mask, gt_mean, gt_std, out);
}

// round 4
// speedup vs baseline: 1.4714x; 1.1677x over previous
#include <cuda_runtime.h>

#define HWD (96*96*96)        // 884736
#define NB  4
#define NVOX (NB*HWD)         // 3538944
#define Q4  (HWD/4)           // 221184 float4 groups per (b, channel)
#define BLOCK 256
#define GRID  (NVOX / 4 / BLOCK)   // 3456, exact

__device__ double       g_sum    = 0.0;
__device__ int          g_cnt    = 0;
__device__ unsigned int g_retire = 0u;

// acos via Abramowitz-Stegun 4.4.45 (4 coeff): abs err <= 6.7e-5 rad.
// Input r is pre-clamped to [-1+1e-7, 1-1e-7], so 1-|r| >= ~1e-7.
__device__ __forceinline__ float fast_acosf(float x) {
    float ax = fabsf(x);
    float t  = 1.0f - ax;
    float s  = t * rsqrtf(t);                 // sqrt(1-ax), MUFU.RSQ
    float p  = fmaf(ax, -0.0187293f, 0.0742610f);
    p = fmaf(ax, p, -0.2121144f);
    p = fmaf(ax, p,  1.5707288f);
    float a = s * p;
    return (x >= 0.0f) ? a : (3.14159265358979f - a);
}

// Given 6 unique entries of a symmetric 3x3: q (mean eig), p (spread),
// cp = cos(acos(r)/3). Normalization folded into det via rs^3.
__device__ __forceinline__ void eig_qpc(
    float a00, float a01, float a02, float a11, float a12, float a22,
    float& q, float& p, float& cp)
{
    q = (a00 + a11 + a22) * (1.0f / 3.0f);
    float c00 = a00 - q, c11 = a11 - q, c22 = a22 - q;
    float p2 = c00*c00 + c11*c11 + c22*c22
             + 2.0f * (a01*a01 + a02*a02 + a12*a12);
    float p2s = p2 * (1.0f / 6.0f);
    float rs  = (p2s > 0.0f) ? rsqrtf(p2s) : 0.0f;   // MUFU.RSQ
    p = p2s * rs;                                     // = sqrt(p2/6)

    float detC = c00 * (c11*c22 - a12*a12)
               - a01 * (a01*c22 - a12*a02)
               + a02 * (a01*a12 - c11*a02);
    float rs3 = rs * rs * rs;
    float r = 0.5f * detC * rs3;
    r = fminf(fmaxf(r, -1.0f + 1e-7f), 1.0f - 1e-7f);
    float phi = fast_acosf(r) * (1.0f / 3.0f);
    cp = __cosf(phi);   // phi in [0, pi/3]
}

__device__ __forceinline__ float f4_get(const float4& v, int lane) {
    switch (lane) {
        case 0: return v.x;
        case 1: return v.y;
        case 2: return v.z;
        default: return v.w;
    }
}

__global__ void __launch_bounds__(BLOCK, 5)
ani_loss_kernel(const float*  __restrict__ input,
                const float*  __restrict__ target,
                const int*    __restrict__ mask,
                const float*  __restrict__ gt_mean,
                const float*  __restrict__ gt_std,
                float*        __restrict__ out)
{
    int i = blockIdx.x * blockDim.x + threadIdx.x;   // one thread = 4 voxels
    int b = i / Q4;
    int s = i - b * Q4;

    const float4* in4 = (const float4*)input;
    const float4* tg4 = (const float4*)target;
    const int4*   mk4 = (const int4*)mask;

    float mean[6], stdv[6];
    #pragma unroll
    for (int c = 0; c < 6; c++) {
        mean[c] = __ldg(&gt_mean[c]);
        stdv[c] = __ldg(&gt_std[c]);
    }

    // ---- phase 1: mask + input channels -> per-lane input anisotropy ----
    int4 mi = __ldcs(&mk4[b * Q4 + s]);

    float4 x[6];
    #pragma unroll
    for (int c = 0; c < 6; c++)
        x[c] = __ldcs(&in4[(b * 6 + c) * Q4 + s]);

    float iani[4];
    #pragma unroll
    for (int lane = 0; lane < 4; lane++) {
        float a[6];
        #pragma unroll
        for (int c = 0; c < 6; c++)
            a[c] = fmaf(f4_get(x[c], lane), stdv[c], mean[c]);
        float q, p, cp;
        eig_qpc(a[0], a[1], a[2], a[3], a[4], a[5], q, p, cp);
        iani[lane] = 3.0f * p * cp;          // l2 - 0.5*(l0+l1) = 3*p*cos(phi)
    }

    // ---- phase 2: target channels -> difference, masked accumulate ----
    #pragma unroll
    for (int c = 0; c < 6; c++)
        x[c] = __ldcs(&tg4[(b * 6 + c) * Q4 + s]);

    int mlane[4] = {mi.x, mi.y, mi.z, mi.w};
    float lsum = 0.0f;
    int   lcnt = 0;

    #pragma unroll
    for (int lane = 0; lane < 4; lane++) {
        float a[6];
        #pragma unroll
        for (int c = 0; c < 6; c++)
            a[c] = fmaf(f4_get(x[c], lane), stdv[c], mean[c]);
        float q, p, cp;
        eig_qpc(a[0], a[1], a[2], a[3], a[4], a[5], q, p, cp);
        float tani = q - p * cp;             // 0.5*(l0+l1)
        float mf = (float)mlane[lane];
        lsum += fabsf(iani[lane] - tani) * mf;
        lcnt += mlane[lane];
    }

    // ---- reduction ----
    #pragma unroll
    for (int o = 16; o > 0; o >>= 1) {
        lsum += __shfl_down_sync(0xFFFFFFFFu, lsum, o);
        lcnt += __shfl_down_sync(0xFFFFFFFFu, lcnt, o);
    }

    __shared__ float ssum[8];
    __shared__ int   scnt[8];
    __shared__ bool  isLast;
    int wid = threadIdx.x >> 5;
    int lid = threadIdx.x & 31;
    if (lid == 0) { ssum[wid] = lsum; scnt[wid] = lcnt; }
    __syncthreads();

    if (wid == 0) {
        float bs = (lid < (BLOCK >> 5)) ? ssum[lid] : 0.0f;
        int   bc = (lid < (BLOCK >> 5)) ? scnt[lid] : 0;
        #pragma unroll
        for (int o = 4; o > 0; o >>= 1) {
            bs += __shfl_down_sync(0xFFFFFFFFu, bs, o);
            bc += __shfl_down_sync(0xFFFFFFFFu, bc, o);
        }
        if (lid == 0) {
            atomicAdd(&g_sum, (double)bs);
            atomicAdd(&g_cnt, bc);
            __threadfence();
            unsigned t = atomicAdd(&g_retire, 1u);
            isLast = (t == (unsigned)(gridDim.x - 1));
        }
    }
    __syncthreads();

    // Last block finalizes and resets accumulators (graph-replay safe).
    if (isLast && threadIdx.x == 0) {
        double s_tot = atomicAdd(&g_sum, 0.0);
        int    c_tot = atomicAdd(&g_cnt, 0);
        double n = (c_tot < 1) ? 1.0 : (double)c_tot;
        out[0] = (float)(s_tot / n);
        atomicExch((unsigned long long*)&g_sum, 0ull);
        atomicExch(&g_cnt, 0);
        __threadfence();
        atomicExch(&g_retire, 0u);
    }
}

extern "C" void kernel_launch(void* const* d_in, const int* in_sizes, int n_in,
                              void* d_out, int out_size)
{
    const float* input   = (const float*)d_in[0];
    const float* target  = (const float*)d_in[1];
    const int*   mask    = (const int*)d_in[2];
    const float* gt_mean = (const float*)d_in[3];
    const float* gt_std  = (const float*)d_in[4];
    float* out = (float*)d_out;

    ani_loss_kernel<<<GRID, BLOCK>>>(input, target, mask, gt_mean, gt_std, out);
}